// round 5
// baseline (speedup 1.0000x reference)
#include <cuda_runtime.h>
#include <cuda_bf16.h>
#include <math.h>

#define INF_F 1e10f
#define L2E   1.4426950408889634f
#define LN2   0.6931471805599453f

// ---------------- scratch (device globals) -------------------------------------
__device__ float g_norm[3u * 8192u * 64u];                // normalized rows
__device__ float g_cost[32ull * 2056ull * 1024ull];       // diag-major cost * L2E (padded)
__device__ float g_hrow[32][32][1024];                    // bottom row of strip ti
__device__ int   g_prog[32][32];                          // [prob][ti] columns published
__device__ float g_R[32];                                 // DTW results (log2-scaled)

__device__ __forceinline__ float fexp2(float x) {
    float y; asm("ex2.approx.f32 %0, %1;" : "=f"(y) : "f"(x)); return y;
}
__device__ __forceinline__ float flog2(float x) {
    float y; asm("lg2.approx.f32 %0, %1;" : "=f"(y) : "f"(x)); return y;
}
typedef unsigned long long u64;
__device__ __forceinline__ u64 ffma2(u64 a, u64 b, u64 c) {
    u64 d; asm("fma.rn.f32x2 %0, %1, %2, %3;" : "=l"(d) : "l"(a), "l"(b), "l"(c)); return d;
}
__device__ __forceinline__ u64 pack2(float x) {
    u64 d; asm("mov.b64 %0, {%1, %1};" : "=l"(d) : "f"(x)); return d;
}

// ---------------- kernel 0: reset progress counters ------------------------------
__global__ void init_kernel() {
    int t = threadIdx.x;
    if (t < 1024) ((int*)g_prog)[t] = 0;
}

// ---------------- kernel 1: row-wise L2 normalize -------------------------------
__global__ void norm_kernel(const float* __restrict__ A,
                            const float* __restrict__ B,
                            const float* __restrict__ C) {
    const int sel  = blockIdx.y;
    const int lane = threadIdx.x & 31;
    const int row  = blockIdx.x * 8 + (threadIdx.x >> 5);
    const float* src = (sel == 0) ? A : ((sel == 1) ? B : C);

    float2 v = *(const float2*)(src + (size_t)row * 64 + lane * 2);
    float ss = v.x * v.x + v.y * v.y;
    #pragma unroll
    for (int o = 16; o > 0; o >>= 1) ss += __shfl_xor_sync(0xffffffffu, ss, o);
    float scale = 1.0f / fmaxf(sqrtf(ss), 1e-8f);
    float* dst = g_norm + (size_t)sel * (8192u * 64u) + (size_t)row * 64 + lane * 2;
    *(float2*)dst = make_float2(v.x * scale, v.y * scale);
}

// ---------------- kernel 2: cost = L2E*(1 - dot), DIAGONAL-major -----------------
// grid (16,16,32), 64 threads, 8x8 microtile, packed f32x2 FMA
__global__ void __launch_bounds__(64) cost_kernel() {
    const int pb   = blockIdx.z;
    const int p    = pb >> 3;
    const int bat  = pb & 7;
    const int asel = p >> 1;                 // TGT(0)/OTH(1)
    const int bsel = (p & 1) ? asel : 2;     // self or X(2)

    const float* Abase = g_norm + ((size_t)asel * 8192u + (size_t)bat * 1024u) * 64u;
    const float* Bbase = g_norm + ((size_t)bsel * 8192u + (size_t)bat * 1024u) * 64u;
    const int i0 = blockIdx.x * 64;
    const int j0 = blockIdx.y * 64;

    __shared__ float sAT[64 * 64];
    __shared__ float sBT[64 * 64];
    const int tid = threadIdx.x;

    {
        const float4* ap = (const float4*)(Abase + (size_t)(i0 + tid) * 64);
        const float4* bp = (const float4*)(Bbase + (size_t)(j0 + tid) * 64);
        #pragma unroll
        for (int q = 0; q < 16; q++) {
            float4 va = ap[q];
            sAT[(4 * q + 0) * 64 + tid] = va.x;
            sAT[(4 * q + 1) * 64 + tid] = va.y;
            sAT[(4 * q + 2) * 64 + tid] = va.z;
            sAT[(4 * q + 3) * 64 + tid] = va.w;
            float4 vb = bp[q];
            sBT[(4 * q + 0) * 64 + tid] = vb.x;
            sBT[(4 * q + 1) * 64 + tid] = vb.y;
            sBT[(4 * q + 2) * 64 + tid] = vb.z;
            sBT[(4 * q + 3) * 64 + tid] = vb.w;
        }
    }
    __syncthreads();

    const int ti = tid >> 3;
    const int tj = tid & 7;

    u64 acc[8][4];
    #pragma unroll
    for (int r = 0; r < 8; r++)
        #pragma unroll
        for (int c = 0; c < 4; c++) acc[r][c] = 0ull;

    #pragma unroll
    for (int k = 0; k < 64; k++) {
        float4 t0 = *(const float4*)&sAT[k * 64 + ti * 8];
        float4 t1 = *(const float4*)&sAT[k * 64 + ti * 8 + 4];
        u64 a2[8];
        a2[0] = pack2(t0.x); a2[1] = pack2(t0.y); a2[2] = pack2(t0.z); a2[3] = pack2(t0.w);
        a2[4] = pack2(t1.x); a2[5] = pack2(t1.y); a2[6] = pack2(t1.z); a2[7] = pack2(t1.w);
        ulonglong2 u0 = *(const ulonglong2*)&sBT[k * 64 + tj * 8];
        ulonglong2 u1 = *(const ulonglong2*)&sBT[k * 64 + tj * 8 + 4];
        u64 b2[4] = {u0.x, u0.y, u1.x, u1.y};
        #pragma unroll
        for (int r = 0; r < 8; r++)
            #pragma unroll
            for (int c = 0; c < 4; c++)
                acc[r][c] = ffma2(a2[r], b2[c], acc[r][c]);
    }
    __syncthreads();

    // restage to shared (alias sAT) with the affine transform applied
    float* Cs = sAT;
    #pragma unroll
    for (int r = 0; r < 8; r++) {
        float v[8];
        #pragma unroll
        for (int c = 0; c < 4; c++) {
            float lo, hi;
            asm("mov.b64 {%0, %1}, %2;" : "=f"(lo), "=f"(hi) : "l"(acc[r][c]));
            v[2 * c]     = fmaf(lo, -L2E, L2E);
            v[2 * c + 1] = fmaf(hi, -L2E, L2E);
        }
        *(float4*)&Cs[(ti * 8 + r) * 64 + tj * 8]     = make_float4(v[0], v[1], v[2], v[3]);
        *(float4*)&Cs[(ti * 8 + r) * 64 + tj * 8 + 4] = make_float4(v[4], v[5], v[6], v[7]);
    }
    __syncthreads();

    // scatter into diagonal-major global layout (coalesced per diagonal)
    float* out = g_cost + (size_t)pb * (2056ull * 1024ull);
    const int kbase = i0 + j0;
    for (int d = 0; d < 127; d++) {
        int lo = d - 63; if (lo < 0) lo = 0;
        int hi = d;      if (hi > 63) hi = 63;
        int i = lo + tid;
        if (i <= hi)
            out[(size_t)(kbase + d) * 1024u + (i0 + i)] = Cs[i * 64 + (d - i)];
    }
}

// ---------------- kernel 3: soft-DTW, continuous-skew strip pipeline -------------
// warp (prob, ti): step s computes cell (row=lane, col=s-lane). 1056 steps/strip.
// cost streamed via diagonal-major coalesced LDG; halo via global + release/acquire.
__global__ void __launch_bounds__(128) dp_kernel() {
    const int wslot = threadIdx.x >> 5;
    const int wid   = blockIdx.x * 4 + wslot;     // 0..1023
    const int lane  = threadIdx.x & 31;
    const int prob  = wid >> 5;
    const int ti    = wid & 31;

    const float* cptr = g_cost + ((size_t)prob * 2056u + (unsigned)(ti * 32)) * 1024u
                      + ti * 32 + lane;
    const float* hin       = &g_hrow[prob][(ti > 0) ? (ti - 1) : 0][0];
    float*       hout      = &g_hrow[prob][ti][0];
    int*         prog_prev = &g_prog[prob][(ti > 0) ? (ti - 1) : 0];
    int*         prog_self = &g_prog[prob][ti];
    const bool   has_up    = (ti > 0);

    float r_cur = INF_F, r_prev = INF_F, up = INF_F, dgs = INF_F;
    float corner = (ti == 0) ? 0.0f : INF_F;     // R_above[-1]; R[-1][-1]=0 for ti=0

    float c[8], h[8];
    #pragma unroll
    for (int k = 0; k < 8; k++) h[k] = INF_F;

    int avail = 0;
    if (has_up && lane == 0) {
        while (avail < 8)
            asm volatile("ld.acquire.gpu.global.s32 %0, [%1];" : "=r"(avail) : "l"(prog_prev));
        #pragma unroll
        for (int k = 0; k < 8; k++) h[k] = __ldcg(hin + k);
    }
    #pragma unroll
    for (int k = 0; k < 8; k++) c[k] = __ldg(cptr + (size_t)k * 1024u);

    for (int g = 0; g < 132; g++) {
        const int s0 = g * 8;

        // ensure next-group halo prefetches are published (lane 0 only; sleepless)
        if (has_up && lane == 0) {
            int need = s0 + 16; if (need > 1024) need = 1024;
            while (avail < need)
                asm volatile("ld.acquire.gpu.global.s32 %0, [%1];" : "=r"(avail) : "l"(prog_prev));
        }

        #pragma unroll
        for (int k = 0; k < 8; k++) {
            const int s  = s0 + k;
            float Dv = c[k];
            float hu = h[k];
            // prefetch for group g+1 (8 steps ahead; covers DRAM latency)
            c[k] = __ldg(cptr + (size_t)(s + 8) * 1024u);
            if (has_up && lane == 0) {
                int hidx = s + 8; if (hidx > 1023) hidx = 1023;
                h[k] = __ldcg(hin + hidx);
            }

            float u = up, dg = dgs;
            if (lane == 0) { u = hu; dg = corner; corner = hu; }

            float p   = fminf(u, dg);
            float q   = fmaxf(u, dg);
            float mn  = fminf(p, r_cur);
            float mx  = fmaxf(q, r_cur);
            float mid = fmaxf(p, fminf(q, r_cur));
            float e1  = fexp2(mn - mid);
            float e2  = fexp2(mn - mx);
            float curv = (Dv + mn) - flog2((1.0f + e1) + e2);

            bool  active = ((unsigned)(s - lane) < 1024u);
            float ncur   = active ? curv : r_cur;
            if (lane == 31 && active) hout[s - 31] = ncur;   // bottom-row halo out
            r_prev = active ? r_cur : r_prev;
            r_cur  = ncur;

            up  = __shfl_up_sync(0xffffffffu, r_cur, 1);
            dgs = __shfl_up_sync(0xffffffffu, r_prev, 1);
        }

        // publish progress (release orders the halo STGs above)
        if (lane == 31) {
            int cnt = 8 * g - 23;                 // columns lane31 has completed
            if (cnt > 1024) cnt = 1024;
            if (cnt > 0)
                asm volatile("st.release.gpu.global.s32 [%0], %1;"
                             :: "l"(prog_self), "r"(cnt) : "memory");
        }
    }

    if (ti == 31 && lane == 31) g_R[prob] = r_cur;    // R[1023][1023]
}

// ---------------- kernel 4: combine into MSE loss --------------------------------
__global__ void combine_kernel(const float* __restrict__ labels, float* __restrict__ out) {
    const int b = threadIdx.x;
    float v = 0.0f;
    if (b < 8) {
        float sTX = g_R[0 * 8 + b];
        float sTT = g_R[1 * 8 + b];
        float sOX = g_R[2 * 8 + b];
        float sOO = g_R[3 * 8 + b];
        float diff = ((sTX - sOX) - 0.5f * (sTT - sOO)) * LN2 - labels[0];
        v = diff * diff;
    }
    #pragma unroll
    for (int o = 4; o > 0; o >>= 1) v += __shfl_down_sync(0xffffffffu, v, o);
    if (b == 0) out[0] = v * 0.125f;
}

// ---------------- launcher -------------------------------------------------------
extern "C" void kernel_launch(void* const* d_in, const int* in_sizes, int n_in,
                              void* d_out, int out_size) {
    const float* TGT    = (const float*)d_in[0];
    const float* OTH    = (const float*)d_in[1];
    const float* X      = (const float*)d_in[2];
    const float* labels = (const float*)d_in[3];
    float* out = (float*)d_out;

    init_kernel<<<1, 1024>>>();
    norm_kernel<<<dim3(1024, 3), 256>>>(TGT, OTH, X);
    cost_kernel<<<dim3(16, 16, 32), 64>>>();
    dp_kernel<<<256, 128>>>();
    combine_kernel<<<1, 32>>>(labels, out);
}

// round 6
// speedup vs baseline: 1.6477x; 1.6477x over previous
#include <cuda_runtime.h>
#include <cuda_bf16.h>
#include <math.h>

#define INF_F 1e10f
#define L2E   1.4426950408889634f
#define LN2   0.6931471805599453f
#define NDIAG 2072ull

// ---------------- scratch (device globals) -------------------------------------
__device__ float g_norm[3u * 8192u * 64u];               // normalized rows
__device__ float g_cost[32ull * NDIAG * 1024ull];        // diag-major cost * L2E (padded)
__device__ float g_hrow[32][32][1024];                   // bottom row of strip ti
__device__ int   g_prog[32][32];                         // [prob][ti] columns published
__device__ float g_R[32];                                // DTW results (log2-scaled)

__device__ __forceinline__ float fexp2(float x) {
    float y; asm("ex2.approx.f32 %0, %1;" : "=f"(y) : "f"(x)); return y;
}
__device__ __forceinline__ float flog2(float x) {
    float y; asm("lg2.approx.f32 %0, %1;" : "=f"(y) : "f"(x)); return y;
}
typedef unsigned long long u64;
__device__ __forceinline__ u64 ffma2(u64 a, u64 b, u64 c) {
    u64 d; asm("fma.rn.f32x2 %0, %1, %2, %3;" : "=l"(d) : "l"(a), "l"(b), "l"(c)); return d;
}
__device__ __forceinline__ u64 pack2(float x) {
    u64 d; asm("mov.b64 %0, {%1, %1};" : "=l"(d) : "f"(x)); return d;
}

// ---------------- kernel 0: reset progress counters ------------------------------
__global__ void init_kernel() {
    int t = threadIdx.x;
    if (t < 1024) ((int*)g_prog)[t] = 0;
}

// ---------------- kernel 1: row-wise L2 normalize -------------------------------
__global__ void norm_kernel(const float* __restrict__ A,
                            const float* __restrict__ B,
                            const float* __restrict__ C) {
    const int sel  = blockIdx.y;
    const int lane = threadIdx.x & 31;
    const int row  = blockIdx.x * 8 + (threadIdx.x >> 5);
    const float* src = (sel == 0) ? A : ((sel == 1) ? B : C);

    float2 v = *(const float2*)(src + (size_t)row * 64 + lane * 2);
    float ss = v.x * v.x + v.y * v.y;
    #pragma unroll
    for (int o = 16; o > 0; o >>= 1) ss += __shfl_xor_sync(0xffffffffu, ss, o);
    float scale = 1.0f / fmaxf(sqrtf(ss), 1e-8f);
    float* dst = g_norm + (size_t)sel * (8192u * 64u) + (size_t)row * 64 + lane * 2;
    *(float2*)dst = make_float2(v.x * scale, v.y * scale);
}

// ---------------- kernel 2: cost = L2E*(1 - dot), DIAGONAL-major -----------------
__global__ void __launch_bounds__(64) cost_kernel() {
    const int pb   = blockIdx.z;
    const int p    = pb >> 3;
    const int bat  = pb & 7;
    const int asel = p >> 1;                 // TGT(0)/OTH(1)
    const int bsel = (p & 1) ? asel : 2;     // self or X(2)

    const float* Abase = g_norm + ((size_t)asel * 8192u + (size_t)bat * 1024u) * 64u;
    const float* Bbase = g_norm + ((size_t)bsel * 8192u + (size_t)bat * 1024u) * 64u;
    const int i0 = blockIdx.x * 64;
    const int j0 = blockIdx.y * 64;

    __shared__ float sAT[64 * 64];
    __shared__ float sBT[64 * 64];
    const int tid = threadIdx.x;

    {
        const float4* ap = (const float4*)(Abase + (size_t)(i0 + tid) * 64);
        const float4* bp = (const float4*)(Bbase + (size_t)(j0 + tid) * 64);
        #pragma unroll
        for (int q = 0; q < 16; q++) {
            float4 va = ap[q];
            sAT[(4 * q + 0) * 64 + tid] = va.x;
            sAT[(4 * q + 1) * 64 + tid] = va.y;
            sAT[(4 * q + 2) * 64 + tid] = va.z;
            sAT[(4 * q + 3) * 64 + tid] = va.w;
            float4 vb = bp[q];
            sBT[(4 * q + 0) * 64 + tid] = vb.x;
            sBT[(4 * q + 1) * 64 + tid] = vb.y;
            sBT[(4 * q + 2) * 64 + tid] = vb.z;
            sBT[(4 * q + 3) * 64 + tid] = vb.w;
        }
    }
    __syncthreads();

    const int ti = tid >> 3;
    const int tj = tid & 7;

    u64 acc[8][4];
    #pragma unroll
    for (int r = 0; r < 8; r++)
        #pragma unroll
        for (int c = 0; c < 4; c++) acc[r][c] = 0ull;

    #pragma unroll
    for (int k = 0; k < 64; k++) {
        float4 t0 = *(const float4*)&sAT[k * 64 + ti * 8];
        float4 t1 = *(const float4*)&sAT[k * 64 + ti * 8 + 4];
        u64 a2[8];
        a2[0] = pack2(t0.x); a2[1] = pack2(t0.y); a2[2] = pack2(t0.z); a2[3] = pack2(t0.w);
        a2[4] = pack2(t1.x); a2[5] = pack2(t1.y); a2[6] = pack2(t1.z); a2[7] = pack2(t1.w);
        ulonglong2 u0 = *(const ulonglong2*)&sBT[k * 64 + tj * 8];
        ulonglong2 u1 = *(const ulonglong2*)&sBT[k * 64 + tj * 8 + 4];
        u64 b2[4] = {u0.x, u0.y, u1.x, u1.y};
        #pragma unroll
        for (int r = 0; r < 8; r++)
            #pragma unroll
            for (int c = 0; c < 4; c++)
                acc[r][c] = ffma2(a2[r], b2[c], acc[r][c]);
    }
    __syncthreads();

    float* Cs = sAT;   // restage (alias) with affine transform applied
    #pragma unroll
    for (int r = 0; r < 8; r++) {
        float v[8];
        #pragma unroll
        for (int c = 0; c < 4; c++) {
            float lo, hi;
            asm("mov.b64 {%0, %1}, %2;" : "=f"(lo), "=f"(hi) : "l"(acc[r][c]));
            v[2 * c]     = fmaf(lo, -L2E, L2E);
            v[2 * c + 1] = fmaf(hi, -L2E, L2E);
        }
        *(float4*)&Cs[(ti * 8 + r) * 64 + tj * 8]     = make_float4(v[0], v[1], v[2], v[3]);
        *(float4*)&Cs[(ti * 8 + r) * 64 + tj * 8 + 4] = make_float4(v[4], v[5], v[6], v[7]);
    }
    __syncthreads();

    float* out = g_cost + (size_t)pb * (NDIAG * 1024ull);
    const int kbase = i0 + j0;
    for (int d = 0; d < 127; d++) {
        int lo = d - 63; if (lo < 0) lo = 0;
        int hi = d;      if (hi > 63) hi = 63;
        int i = lo + tid;
        if (i <= hi)
            out[(size_t)(kbase + d) * 1024u + (i0 + i)] = Cs[i * 64 + (d - i)];
    }
}

// ---------------- kernel 3: soft-DTW, continuous skew, divergence-free ----------
// warp (prob, ti): step s, lane l computes cell (row=l, col=s-l). 1056 steps.
// NO divergent branch in the steady loop: halo via uniform spin + shfl broadcast,
// cost via 16-deep static register pipe, halo-out / publish via predicated stores.
__global__ void __launch_bounds__(128) dp_kernel() {
    const int wslot = threadIdx.x >> 5;
    const int wid   = blockIdx.x * 4 + wslot;     // 0..1023
    const int lane  = threadIdx.x & 31;
    const int prob  = wid >> 5;
    const int ti    = wid & 31;
    const bool has_up = (ti > 0);

    // cost stream: diag = 32*ti + s, element (row) = 32*ti + lane
    const float* cbase = g_cost + ((size_t)prob * NDIAG + (unsigned)(32 * ti)) * 1024ull
                       + 32 * ti + lane;
    const float* hin       = &g_hrow[prob][has_up ? (ti - 1) : 0][0];
    float*       hout      = &g_hrow[prob][ti][0];
    int*         prog_prev = &g_prog[prob][has_up ? (ti - 1) : 0];
    int*         prog_self = &g_prog[prob][ti];

    // 16-deep cost pipe (static indices -> registers)
    float c[16];
    #pragma unroll
    for (int k = 0; k < 16; k++) c[k] = __ldg(cbase + (size_t)k * 1024u);

    float hval   = INF_F;                       // halo slice: hin[s0 + (lane&7)]
    float r_cur  = INF_F, r_prev = INF_F;
    float up     = INF_F, dgs    = INF_F;
    float corner = (ti == 0) ? 0.0f : INF_F;    // R_above[s-1] for lane 0

    for (int g = 0; g < 132; g++) {
        const int s0 = g * 8;

        if (has_up) {
            // uniform warp-wide spin: one coalesced acquire load per poll
            int need = s0 + 8; if (need > 1024) need = 1024;
            int avail;
            do {
                asm volatile("ld.acquire.gpu.global.s32 %0, [%1];"
                             : "=r"(avail) : "l"(prog_prev));
            } while (avail < need);
            int hidx = s0 + (lane & 7); if (hidx > 1023) hidx = 1023;
            hval = __ldcg(hin + hidx);          // uniform: 8 distinct addrs, 1 sector
        }

        const int slot0 = (g & 1) << 3;         // rotating half of the 16-deep pipe
        #pragma unroll
        for (int k = 0; k < 8; k++) {
            const int s = s0 + k;
            float Dv = c[slot0 + k];
            c[slot0 + k] = __ldg(cbase + (size_t)(s + 16) * 1024u);   // prefetch

            float topv = __shfl_sync(0xffffffffu, hval, k);           // broadcast
            float u = up, dg = dgs;
            if (lane == 0) { u = topv; dg = corner; }
            corner = topv;                       // only lane 0 ever reads it

            float p   = fminf(u, dg);
            float q   = fmaxf(u, dg);
            float mn  = fminf(p, r_cur);
            float mx  = fmaxf(q, r_cur);
            float mid = fmaxf(p, fminf(q, r_cur));
            float e1  = fexp2(mn - mid);
            float e2  = fexp2(mn - mx);
            float curv = (Dv + mn) - flog2((1.0f + e1) + e2);

            bool  active = ((unsigned)(s - lane) < 1024u);
            float ncur   = active ? curv : r_cur;
            if (lane == 31 && active) hout[s - 31] = ncur;   // predicated STG
            r_prev = active ? r_cur : r_prev;
            r_cur  = ncur;

            up  = __shfl_up_sync(0xffffffffu, r_cur, 1);
            dgs = __shfl_up_sync(0xffffffffu, r_prev, 1);
        }

        // publish progress (release orders lane 31's halo stores); predicated
        {
            int cnt = 8 * g - 23; if (cnt > 1024) cnt = 1024;
            asm volatile(
                "{ .reg .pred p;\n\t"
                "  setp.eq.s32 p, %2, 31;\n\t"
                "  setp.gt.and.s32 p, %1, 0, p;\n\t"
                "  @p st.release.gpu.global.s32 [%0], %1; }"
                :: "l"(prog_self), "r"(cnt), "r"(lane) : "memory");
        }
    }

    if (ti == 31 && lane == 31) g_R[prob] = r_cur;    // R[1023][1023]
}

// ---------------- kernel 4: combine into MSE loss --------------------------------
__global__ void combine_kernel(const float* __restrict__ labels, float* __restrict__ out) {
    const int b = threadIdx.x;
    float v = 0.0f;
    if (b < 8) {
        float sTX = g_R[0 * 8 + b];
        float sTT = g_R[1 * 8 + b];
        float sOX = g_R[2 * 8 + b];
        float sOO = g_R[3 * 8 + b];
        float diff = ((sTX - sOX) - 0.5f * (sTT - sOO)) * LN2 - labels[0];
        v = diff * diff;
    }
    #pragma unroll
    for (int o = 4; o > 0; o >>= 1) v += __shfl_down_sync(0xffffffffu, v, o);
    if (b == 0) out[0] = v * 0.125f;
}

// ---------------- launcher -------------------------------------------------------
extern "C" void kernel_launch(void* const* d_in, const int* in_sizes, int n_in,
                              void* d_out, int out_size) {
    const float* TGT    = (const float*)d_in[0];
    const float* OTH    = (const float*)d_in[1];
    const float* X      = (const float*)d_in[2];
    const float* labels = (const float*)d_in[3];
    float* out = (float*)d_out;

    init_kernel<<<1, 1024>>>();
    norm_kernel<<<dim3(1024, 3), 256>>>(TGT, OTH, X);
    cost_kernel<<<dim3(16, 16, 32), 64>>>();
    dp_kernel<<<256, 128>>>();
    combine_kernel<<<1, 32>>>(labels, out);
}

// round 7
// speedup vs baseline: 2.6999x; 1.6386x over previous
#include <cuda_runtime.h>
#include <cuda_bf16.h>
#include <math.h>

#define INF_F 1e10f
#define L2E   1.4426950408889634f
#define LN2   0.6931471805599453f
#define NDIAG 2072ull
#define SENT_U 0x7FC00000u

// ---------------- scratch (device globals) -------------------------------------
__device__ float g_norm[3u * 8192u * 64u];               // normalized rows
__device__ float g_cost[32ull * NDIAG * 1024ull];        // diag-major cost * L2E (padded)
__device__ float g_hrow[32][32][1024];                   // bottom row of strip ti (sentinel-init)
__device__ float g_R[32];                                // DTW results (log2-scaled)

__device__ __forceinline__ float fexp2(float x) {
    float y; asm("ex2.approx.f32 %0, %1;" : "=f"(y) : "f"(x)); return y;
}
__device__ __forceinline__ float flog2(float x) {
    float y; asm("lg2.approx.f32 %0, %1;" : "=f"(y) : "f"(x)); return y;
}
__device__ __forceinline__ float ld_rlx(const float* p) {
    float v; asm volatile("ld.relaxed.gpu.global.f32 %0, [%1];" : "=f"(v) : "l"(p)); return v;
}
__device__ __forceinline__ void st_rlx(float* p, float v) {
    asm volatile("st.relaxed.gpu.global.f32 [%0], %1;" :: "l"(p), "f"(v) : "memory");
}
typedef unsigned long long u64;
__device__ __forceinline__ u64 ffma2(u64 a, u64 b, u64 c) {
    u64 d; asm("fma.rn.f32x2 %0, %1, %2, %3;" : "=l"(d) : "l"(a), "l"(b), "l"(c)); return d;
}
__device__ __forceinline__ u64 pack2(float x) {
    u64 d; asm("mov.b64 %0, {%1, %1};" : "=l"(d) : "f"(x)); return d;
}

// ---------------- kernel 0: fill halo buffer with sentinel -----------------------
__global__ void init_kernel() {
    unsigned t = blockIdx.x * 512u + threadIdx.x;        // 1,048,576 words
    ((unsigned*)g_hrow)[t] = SENT_U;
}

// ---------------- kernel 1: row-wise L2 normalize -------------------------------
__global__ void norm_kernel(const float* __restrict__ A,
                            const float* __restrict__ B,
                            const float* __restrict__ C) {
    const int sel  = blockIdx.y;
    const int lane = threadIdx.x & 31;
    const int row  = blockIdx.x * 8 + (threadIdx.x >> 5);
    const float* src = (sel == 0) ? A : ((sel == 1) ? B : C);

    float2 v = *(const float2*)(src + (size_t)row * 64 + lane * 2);
    float ss = v.x * v.x + v.y * v.y;
    #pragma unroll
    for (int o = 16; o > 0; o >>= 1) ss += __shfl_xor_sync(0xffffffffu, ss, o);
    float scale = 1.0f / fmaxf(sqrtf(ss), 1e-8f);
    float* dst = g_norm + (size_t)sel * (8192u * 64u) + (size_t)row * 64 + lane * 2;
    *(float2*)dst = make_float2(v.x * scale, v.y * scale);
}

// ---------------- kernel 2: cost = L2E*(1 - dot), DIAGONAL-major -----------------
__global__ void __launch_bounds__(64) cost_kernel() {
    const int pb   = blockIdx.z;
    const int p    = pb >> 3;
    const int bat  = pb & 7;
    const int asel = p >> 1;                 // TGT(0)/OTH(1)
    const int bsel = (p & 1) ? asel : 2;     // self or X(2)

    const float* Abase = g_norm + ((size_t)asel * 8192u + (size_t)bat * 1024u) * 64u;
    const float* Bbase = g_norm + ((size_t)bsel * 8192u + (size_t)bat * 1024u) * 64u;
    const int i0 = blockIdx.x * 64;
    const int j0 = blockIdx.y * 64;

    __shared__ float sAT[64 * 64];
    __shared__ float sBT[64 * 64];
    const int tid = threadIdx.x;

    {
        const float4* ap = (const float4*)(Abase + (size_t)(i0 + tid) * 64);
        const float4* bp = (const float4*)(Bbase + (size_t)(j0 + tid) * 64);
        #pragma unroll
        for (int q = 0; q < 16; q++) {
            float4 va = ap[q];
            sAT[(4 * q + 0) * 64 + tid] = va.x;
            sAT[(4 * q + 1) * 64 + tid] = va.y;
            sAT[(4 * q + 2) * 64 + tid] = va.z;
            sAT[(4 * q + 3) * 64 + tid] = va.w;
            float4 vb = bp[q];
            sBT[(4 * q + 0) * 64 + tid] = vb.x;
            sBT[(4 * q + 1) * 64 + tid] = vb.y;
            sBT[(4 * q + 2) * 64 + tid] = vb.z;
            sBT[(4 * q + 3) * 64 + tid] = vb.w;
        }
    }
    __syncthreads();

    const int ti = tid >> 3;
    const int tj = tid & 7;

    u64 acc[8][4];
    #pragma unroll
    for (int r = 0; r < 8; r++)
        #pragma unroll
        for (int c = 0; c < 4; c++) acc[r][c] = 0ull;

    #pragma unroll
    for (int k = 0; k < 64; k++) {
        float4 t0 = *(const float4*)&sAT[k * 64 + ti * 8];
        float4 t1 = *(const float4*)&sAT[k * 64 + ti * 8 + 4];
        u64 a2[8];
        a2[0] = pack2(t0.x); a2[1] = pack2(t0.y); a2[2] = pack2(t0.z); a2[3] = pack2(t0.w);
        a2[4] = pack2(t1.x); a2[5] = pack2(t1.y); a2[6] = pack2(t1.z); a2[7] = pack2(t1.w);
        ulonglong2 u0 = *(const ulonglong2*)&sBT[k * 64 + tj * 8];
        ulonglong2 u1 = *(const ulonglong2*)&sBT[k * 64 + tj * 8 + 4];
        u64 b2[4] = {u0.x, u0.y, u1.x, u1.y};
        #pragma unroll
        for (int r = 0; r < 8; r++)
            #pragma unroll
            for (int c = 0; c < 4; c++)
                acc[r][c] = ffma2(a2[r], b2[c], acc[r][c]);
    }
    __syncthreads();

    float* Cs = sAT;   // restage (alias) with affine transform applied
    #pragma unroll
    for (int r = 0; r < 8; r++) {
        float v[8];
        #pragma unroll
        for (int c = 0; c < 4; c++) {
            float lo, hi;
            asm("mov.b64 {%0, %1}, %2;" : "=f"(lo), "=f"(hi) : "l"(acc[r][c]));
            v[2 * c]     = fmaf(lo, -L2E, L2E);
            v[2 * c + 1] = fmaf(hi, -L2E, L2E);
        }
        *(float4*)&Cs[(ti * 8 + r) * 64 + tj * 8]     = make_float4(v[0], v[1], v[2], v[3]);
        *(float4*)&Cs[(ti * 8 + r) * 64 + tj * 8 + 4] = make_float4(v[4], v[5], v[6], v[7]);
    }
    __syncthreads();

    float* out = g_cost + (size_t)pb * (NDIAG * 1024ull);
    const int kbase = i0 + j0;
    for (int d = 0; d < 127; d++) {
        int lo = d - 63; if (lo < 0) lo = 0;
        int hi = d;      if (hi > 63) hi = 63;
        int i = lo + tid;
        if (i <= hi)
            out[(size_t)(kbase + d) * 1024u + (i0 + i)] = Cs[i * 64 + (d - i)];
    }
}

// ---------------- kernel 3: soft-DTW, continuous skew, sentinel handoff ----------
// warp (prob, ti): step s, lane l computes cell (row=l, col=s-l). 1056 steps.
// Halo published word-by-word (relaxed, L2); "published" detected by non-sentinel
// bits. Loads for group g+2 issued during group g; verified (register ballot) at
// group g+1 end — zero memory latency on the steady-state critical path.
__global__ void __launch_bounds__(128) dp_kernel() {
    const int wslot = threadIdx.x >> 5;
    const int wid   = blockIdx.x * 4 + wslot;     // 0..1023
    const int lane  = threadIdx.x & 31;
    const int prob  = wid >> 5;
    const int ti    = wid & 31;
    const bool has_up = (ti > 0);

    const float* cbase = g_cost + ((size_t)prob * NDIAG + (unsigned)(32 * ti)) * 1024ull
                       + 32 * ti + lane;
    const float* hin  = &g_hrow[prob][has_up ? (ti - 1) : 0][0];
    float*       hout = &g_hrow[prob][ti][0];
    const int    lid8 = lane & 7;

    // 16-deep cost register pipe
    float c[16];
    #pragma unroll
    for (int k = 0; k < 16; k++) c[k] = __ldg(cbase + (size_t)k * 1024u);

    float r_cur  = INF_F, r_prev = INF_F;
    float up     = INF_F, dgs    = INF_F;
    float corner = (ti == 0) ? 0.0f : INF_F;

    // halo slots: hcur = verified data for current group; hnxt = unverified next
    float hcur = INF_F, hnxt = 0.0f;
    if (has_up) {
        // verified load of group 0 (spin with backoff; fill phase)
        for (;;) {
            hcur = ld_rlx(hin + lid8);
            if (!__any_sync(0xffffffffu, __float_as_uint(hcur) == SENT_U)) break;
            __nanosleep(128);
        }
        hnxt = ld_rlx(hin + 8 + lid8);     // group 1, unverified
    }

    for (int g = 0; g < 132; g++) {
        const int s0    = g * 8;
        const int slot0 = (g & 1) << 3;

        #pragma unroll
        for (int k = 0; k < 8; k++) {
            const int s = s0 + k;
            float Dv = c[slot0 + k];
            c[slot0 + k] = __ldg(cbase + (size_t)(s + 16) * 1024u);   // prefetch

            float topv = __shfl_sync(0xffffffffu, hcur, k);
            float u = up, dg = dgs;
            if (lane == 0) { u = topv; dg = corner; }
            corner = topv;

            float p   = fminf(u, dg);
            float q   = fmaxf(u, dg);
            float mn  = fminf(p, r_cur);
            float mx  = fmaxf(q, r_cur);
            float mid = fmaxf(p, fminf(q, r_cur));
            float e1  = fexp2(mn - mid);
            float e2  = fexp2(mn - mx);
            float curv = (Dv + mn) - flog2((1.0f + e1) + e2);

            bool  active = ((unsigned)(s - lane) < 1024u);
            float ncur   = active ? curv : r_cur;
            if (lane == 31 && active) st_rlx(hout + (s - 31), ncur);  // publish
            r_prev = active ? r_cur : r_prev;
            r_cur  = ncur;

            up  = __shfl_up_sync(0xffffffffu, r_cur, 1);
            dgs = __shfl_up_sync(0xffffffffu, r_prev, 1);
        }

        // advance halo pipeline (uniform): verify g+1, issue load for g+2
        if (has_up) {
            if (g + 1 <= 127) {
                while (__any_sync(0xffffffffu, __float_as_uint(hnxt) == SENT_U)) {
                    __nanosleep(64);
                    hnxt = ld_rlx(hin + (s0 + 8) + lid8);
                }
            }
            hcur = hnxt;
            hnxt = (g + 2 <= 127) ? ld_rlx(hin + (s0 + 16) + lid8) : 0.0f;
        }
    }

    if (ti == 31 && lane == 31) g_R[prob] = r_cur;    // R[1023][1023]
}

// ---------------- kernel 4: combine into MSE loss --------------------------------
__global__ void combine_kernel(const float* __restrict__ labels, float* __restrict__ out) {
    const int b = threadIdx.x;
    float v = 0.0f;
    if (b < 8) {
        float sTX = g_R[0 * 8 + b];
        float sTT = g_R[1 * 8 + b];
        float sOX = g_R[2 * 8 + b];
        float sOO = g_R[3 * 8 + b];
        float diff = ((sTX - sOX) - 0.5f * (sTT - sOO)) * LN2 - labels[0];
        v = diff * diff;
    }
    #pragma unroll
    for (int o = 4; o > 0; o >>= 1) v += __shfl_down_sync(0xffffffffu, v, o);
    if (b == 0) out[0] = v * 0.125f;
}

// ---------------- launcher -------------------------------------------------------
extern "C" void kernel_launch(void* const* d_in, const int* in_sizes, int n_in,
                              void* d_out, int out_size) {
    const float* TGT    = (const float*)d_in[0];
    const float* OTH    = (const float*)d_in[1];
    const float* X      = (const float*)d_in[2];
    const float* labels = (const float*)d_in[3];
    float* out = (float*)d_out;

    init_kernel<<<2048, 512>>>();
    norm_kernel<<<dim3(1024, 3), 256>>>(TGT, OTH, X);
    cost_kernel<<<dim3(16, 16, 32), 64>>>();
    dp_kernel<<<256, 128>>>();
    combine_kernel<<<1, 32>>>(labels, out);
}

// round 8
// speedup vs baseline: 4.1714x; 1.5450x over previous
#include <cuda_runtime.h>
#include <cuda_bf16.h>
#include <math.h>

#define INF_F 1e10f
#define L2E   1.4426950408889634f
#define LN2   0.6931471805599453f
#define NDIAG 2072ull
#define SENT_U 0x7FC00000u

// ---------------- scratch (device globals) -------------------------------------
__device__ float g_norm[3u * 8192u * 64u];               // normalized rows
__device__ float g_cost[32ull * NDIAG * 1024ull];        // diag-major cost * L2E (padded)
__device__ float g_hrow[32][32][1024];                   // bottom row of strip ti (sentinel-init)
__device__ float g_R[32];                                // DTW results (log2-scaled)

__device__ __forceinline__ float fexp2(float x) {
    float y; asm("ex2.approx.f32 %0, %1;" : "=f"(y) : "f"(x)); return y;
}
__device__ __forceinline__ float flog2(float x) {
    float y; asm("lg2.approx.f32 %0, %1;" : "=f"(y) : "f"(x)); return y;
}
__device__ __forceinline__ float ld_rlx(const float* p) {
    float v; asm volatile("ld.relaxed.gpu.global.f32 %0, [%1];" : "=f"(v) : "l"(p)); return v;
}
__device__ __forceinline__ void st_rlx(float* p, float v) {
    asm volatile("st.relaxed.gpu.global.f32 [%0], %1;" :: "l"(p), "f"(v) : "memory");
}
typedef unsigned long long u64;
__device__ __forceinline__ u64 ffma2(u64 a, u64 b, u64 c) {
    u64 d; asm("fma.rn.f32x2 %0, %1, %2, %3;" : "=l"(d) : "l"(a), "l"(b), "l"(c)); return d;
}
__device__ __forceinline__ u64 pack2(float x) {
    u64 d; asm("mov.b64 %0, {%1, %1};" : "=l"(d) : "f"(x)); return d;
}

// ---------------- kernel 0: fill halo buffer with sentinel -----------------------
__global__ void init_kernel() {
    unsigned t = blockIdx.x * 512u + threadIdx.x;        // 1,048,576 words
    ((unsigned*)g_hrow)[t] = SENT_U;
}

// ---------------- kernel 1: row-wise L2 normalize -------------------------------
__global__ void norm_kernel(const float* __restrict__ A,
                            const float* __restrict__ B,
                            const float* __restrict__ C) {
    const int sel  = blockIdx.y;
    const int lane = threadIdx.x & 31;
    const int row  = blockIdx.x * 8 + (threadIdx.x >> 5);
    const float* src = (sel == 0) ? A : ((sel == 1) ? B : C);

    float2 v = *(const float2*)(src + (size_t)row * 64 + lane * 2);
    float ss = v.x * v.x + v.y * v.y;
    #pragma unroll
    for (int o = 16; o > 0; o >>= 1) ss += __shfl_xor_sync(0xffffffffu, ss, o);
    float scale = 1.0f / fmaxf(sqrtf(ss), 1e-8f);
    float* dst = g_norm + (size_t)sel * (8192u * 64u) + (size_t)row * 64 + lane * 2;
    *(float2*)dst = make_float2(v.x * scale, v.y * scale);
}

// ---------------- kernel 2: cost = L2E*(1 - dot), DIAGONAL-major -----------------
__global__ void __launch_bounds__(64) cost_kernel() {
    const int pb   = blockIdx.z;
    const int p    = pb >> 3;
    const int bat  = pb & 7;
    const int asel = p >> 1;                 // TGT(0)/OTH(1)
    const int bsel = (p & 1) ? asel : 2;     // self or X(2)

    const float* Abase = g_norm + ((size_t)asel * 8192u + (size_t)bat * 1024u) * 64u;
    const float* Bbase = g_norm + ((size_t)bsel * 8192u + (size_t)bat * 1024u) * 64u;
    const int i0 = blockIdx.x * 64;
    const int j0 = blockIdx.y * 64;

    __shared__ float sAT[64 * 64];
    __shared__ float sBT[64 * 64];
    const int tid = threadIdx.x;

    {
        const float4* ap = (const float4*)(Abase + (size_t)(i0 + tid) * 64);
        const float4* bp = (const float4*)(Bbase + (size_t)(j0 + tid) * 64);
        #pragma unroll
        for (int q = 0; q < 16; q++) {
            float4 va = ap[q];
            sAT[(4 * q + 0) * 64 + tid] = va.x;
            sAT[(4 * q + 1) * 64 + tid] = va.y;
            sAT[(4 * q + 2) * 64 + tid] = va.z;
            sAT[(4 * q + 3) * 64 + tid] = va.w;
            float4 vb = bp[q];
            sBT[(4 * q + 0) * 64 + tid] = vb.x;
            sBT[(4 * q + 1) * 64 + tid] = vb.y;
            sBT[(4 * q + 2) * 64 + tid] = vb.z;
            sBT[(4 * q + 3) * 64 + tid] = vb.w;
        }
    }
    __syncthreads();

    const int ti = tid >> 3;
    const int tj = tid & 7;

    u64 acc[8][4];
    #pragma unroll
    for (int r = 0; r < 8; r++)
        #pragma unroll
        for (int c = 0; c < 4; c++) acc[r][c] = 0ull;

    #pragma unroll
    for (int k = 0; k < 64; k++) {
        float4 t0 = *(const float4*)&sAT[k * 64 + ti * 8];
        float4 t1 = *(const float4*)&sAT[k * 64 + ti * 8 + 4];
        u64 a2[8];
        a2[0] = pack2(t0.x); a2[1] = pack2(t0.y); a2[2] = pack2(t0.z); a2[3] = pack2(t0.w);
        a2[4] = pack2(t1.x); a2[5] = pack2(t1.y); a2[6] = pack2(t1.z); a2[7] = pack2(t1.w);
        ulonglong2 u0 = *(const ulonglong2*)&sBT[k * 64 + tj * 8];
        ulonglong2 u1 = *(const ulonglong2*)&sBT[k * 64 + tj * 8 + 4];
        u64 b2[4] = {u0.x, u0.y, u1.x, u1.y};
        #pragma unroll
        for (int r = 0; r < 8; r++)
            #pragma unroll
            for (int c = 0; c < 4; c++)
                acc[r][c] = ffma2(a2[r], b2[c], acc[r][c]);
    }
    __syncthreads();

    float* Cs = sAT;   // restage (alias) with affine transform applied
    #pragma unroll
    for (int r = 0; r < 8; r++) {
        float v[8];
        #pragma unroll
        for (int c = 0; c < 4; c++) {
            float lo, hi;
            asm("mov.b64 {%0, %1}, %2;" : "=f"(lo), "=f"(hi) : "l"(acc[r][c]));
            v[2 * c]     = fmaf(lo, -L2E, L2E);
            v[2 * c + 1] = fmaf(hi, -L2E, L2E);
        }
        *(float4*)&Cs[(ti * 8 + r) * 64 + tj * 8]     = make_float4(v[0], v[1], v[2], v[3]);
        *(float4*)&Cs[(ti * 8 + r) * 64 + tj * 8 + 4] = make_float4(v[4], v[5], v[6], v[7]);
    }
    __syncthreads();

    float* out = g_cost + (size_t)pb * (NDIAG * 1024ull);
    const int kbase = i0 + j0;
    for (int d = 0; d < 127; d++) {
        int lo = d - 63; if (lo < 0) lo = 0;
        int hi = d;      if (hi > 63) hi = 63;
        int i = lo + tid;
        if (i <= hi)
            out[(size_t)(kbase + d) * 1024u + (i0 + i)] = Cs[i * 64 + (d - i)];
    }
}

// ---------------- kernel 3: soft-DTW, continuous skew, 3-slot halo pipe ----------
// warp (prob, ti): step s, lane l computes cell (row=l, col=s-l). 1056 steps.
// MODE 0 = lean (all active), 1 = prologue mask (s>=lane), 2 = epilogue mask.
__global__ void __launch_bounds__(128) dp_kernel() {
    const int wslot = threadIdx.x >> 5;
    const int wid   = blockIdx.x * 4 + wslot;     // 0..1023
    const int lane  = threadIdx.x & 31;
    const int prob  = wid >> 5;
    const int ti    = wid & 31;
    const bool has_up = (ti > 0);

    const float* cbase = g_cost + ((size_t)prob * NDIAG + (unsigned)(32 * ti)) * 1024ull
                       + 32 * ti + lane;
    const float* hin  = &g_hrow[prob][has_up ? (ti - 1) : 0][0];
    float*       hout = &g_hrow[prob][ti][0];
    const int    lid8 = lane & 7;

    // 16-deep cost register pipe (static slots)
    float c[16];
    #pragma unroll
    for (int k = 0; k < 16; k++) c[k] = __ldg(cbase + (size_t)k * 1024u);

    float r_cur = INF_F;
    float up    = INF_F;
    float dg    = (ti == 0 && lane == 0) ? 0.0f : INF_F;

    // 3-slot halo pipeline: hv0 current (verified), hv1 next (verified at ROT),
    // hv2 in-flight (loaded 3 groups ahead)
    float hv0 = INF_F, hv1 = 0.0f, hv2 = 0.0f;
    if (has_up) {
        hv0 = ld_rlx(hin + lid8);
        while (__any_sync(0xffffffffu, __float_as_uint(hv0) == SENT_U)) {
            __nanosleep(128);
            hv0 = ld_rlx(hin + lid8);
        }
        hv1 = ld_rlx(hin + 8 + lid8);
        hv2 = ld_rlx(hin + 16 + lid8);
    }

#define DTW_STEP(SLOT0, KK, SS, MODE)                                          \
    {                                                                          \
        float Dv = c[(SLOT0) + (KK)];                                          \
        c[(SLOT0) + (KK)] = __ldg(cbase + (size_t)((SS) + 16) * 1024u);        \
        float topv = __shfl_sync(0xffffffffu, hv0, (KK));                      \
        float u = (lane == 0) ? topv : up;                                     \
        float p   = fminf(u, dg);                                              \
        float q   = fmaxf(u, dg);                                              \
        float mn  = fminf(p, r_cur);                                           \
        float mx  = fmaxf(q, r_cur);                                           \
        float mid = fmaxf(p, fminf(q, r_cur));                                 \
        float e1  = fexp2(mn - mid);                                           \
        float e2  = fexp2(mn - mx);                                            \
        float curv = (Dv + mn) - flog2((1.0f + e1) + e2);                      \
        bool active = (MODE == 0) ? true                                       \
                    : ((MODE == 1) ? ((SS) >= lane)                            \
                                   : (((SS) - lane) <= 1023));                 \
        float ncur = active ? curv : r_cur;                                    \
        if (lane == 31 && active) st_rlx(hout + ((SS) - 31), ncur);            \
        dg    = u;                                                             \
        r_cur = ncur;                                                          \
        up    = __shfl_up_sync(0xffffffffu, r_cur, 1);                         \
    }

#define ROT(G)                                                                 \
    if (has_up && (G) <= 126) {                                                \
        while (__any_sync(0xffffffffu, __float_as_uint(hv1) == SENT_U))        \
            hv1 = ld_rlx(hin + 8 * ((G) + 1) + lid8);                          \
        hv0 = hv1; hv1 = hv2;                                                  \
        int a = 8 * ((G) + 3); if (a > 1016) a = 1016;                         \
        hv2 = ld_rlx(hin + a + lid8);                                          \
    }

    // ---- prologue: groups 0..3 (s = 0..31), masked ----
    #pragma unroll
    for (int kk = 0; kk < 8; kk++) DTW_STEP(0, kk, kk, 1)
    ROT(0)
    #pragma unroll
    for (int kk = 0; kk < 8; kk++) DTW_STEP(8, kk, 8 + kk, 1)
    ROT(1)
    #pragma unroll
    for (int kk = 0; kk < 8; kk++) DTW_STEP(0, kk, 16 + kk, 1)
    ROT(2)
    #pragma unroll
    for (int kk = 0; kk < 8; kk++) DTW_STEP(8, kk, 24 + kk, 1)
    ROT(3)

    // ---- lean steady region: groups 4..127 (s = 32..1023), all lanes active ----
    for (int g = 4; g < 128; g += 2) {
        const int s0 = g * 8;
        #pragma unroll
        for (int kk = 0; kk < 8; kk++) DTW_STEP(0, kk, s0 + kk, 0)
        ROT(g)
        #pragma unroll
        for (int kk = 0; kk < 8; kk++) DTW_STEP(8, kk, s0 + 8 + kk, 0)
        ROT(g + 1)
    }

    // ---- epilogue: groups 128..131 (s = 1024..1055), masked, no halo needed ----
    #pragma unroll
    for (int kk = 0; kk < 8; kk++) DTW_STEP(0, kk, 1024 + kk, 2)
    #pragma unroll
    for (int kk = 0; kk < 8; kk++) DTW_STEP(8, kk, 1032 + kk, 2)
    #pragma unroll
    for (int kk = 0; kk < 8; kk++) DTW_STEP(0, kk, 1040 + kk, 2)
    #pragma unroll
    for (int kk = 0; kk < 8; kk++) DTW_STEP(8, kk, 1048 + kk, 2)

#undef DTW_STEP
#undef ROT

    if (ti == 31 && lane == 31) g_R[prob] = r_cur;    // R[1023][1023]
}

// ---------------- kernel 4: combine into MSE loss --------------------------------
__global__ void combine_kernel(const float* __restrict__ labels, float* __restrict__ out) {
    const int b = threadIdx.x;
    float v = 0.0f;
    if (b < 8) {
        float sTX = g_R[0 * 8 + b];
        float sTT = g_R[1 * 8 + b];
        float sOX = g_R[2 * 8 + b];
        float sOO = g_R[3 * 8 + b];
        float diff = ((sTX - sOX) - 0.5f * (sTT - sOO)) * LN2 - labels[0];
        v = diff * diff;
    }
    #pragma unroll
    for (int o = 4; o > 0; o >>= 1) v += __shfl_down_sync(0xffffffffu, v, o);
    if (b == 0) out[0] = v * 0.125f;
}

// ---------------- launcher -------------------------------------------------------
extern "C" void kernel_launch(void* const* d_in, const int* in_sizes, int n_in,
                              void* d_out, int out_size) {
    const float* TGT    = (const float*)d_in[0];
    const float* OTH    = (const float*)d_in[1];
    const float* X      = (const float*)d_in[2];
    const float* labels = (const float*)d_in[3];
    float* out = (float*)d_out;

    init_kernel<<<2048, 512>>>();
    norm_kernel<<<dim3(1024, 3), 256>>>(TGT, OTH, X);
    cost_kernel<<<dim3(16, 16, 32), 64>>>();
    dp_kernel<<<256, 128>>>();
    combine_kernel<<<1, 32>>>(labels, out);
}